// round 15
// baseline (speedup 1.0000x reference)
#include <cuda_runtime.h>
#include <cuda_fp16.h>
#include <math.h>
#include <stdint.h>

// Problem constants
#define Tn   1536
#define Bn   4
#define Hn   8
#define DKn  64
#define DVn  192
#define Ln   3071          // 2T-1
#define Lp   3072          // padded
#define HDK  512           // H*DK
#define HDV  1536          // H*DV
#define BT   6144          // B*T
#define NBH  32            // B*H
#define Cin  1536

// ---------------- device scratch ----------------
__device__ float  g_pe[Ln * 192];
__device__ float  g_rK[Ln * HDK];
__device__ double g_gmax[32];
__device__ float  g_bR[Hn * Lp];          // (r_r - r_w) . rK  bias table

__device__ float  g_Vf[BT * HDV];

__device__ half   g_xh[BT * Cin], g_xl[BT * Cin];
__device__ half   g_wqkh[1024 * Cin], g_wqkl[1024 * Cin];   // W_q^T | W_k^T concat
__device__ half   g_wvth[HDV * Cin], g_wvtl[HDV * Cin];
__device__ half   g_woth[HDV * HDV], g_wotl[HDV * HDV];

__device__ half   g_qwh[NBH * Tn * DKn], g_qwl[NBH * Tn * DKn];
__device__ half   g_kh [NBH * Tn * DKn], g_kl [NBH * Tn * DKn];
__device__ half   g_rkth[Hn * Lp * DKn], g_rktl[Hn * Lp * DKn];
__device__ half   g_vth[NBH * DVn * Tn], g_vtl[NBH * DVn * Tn];

__device__ float  g_logits[75497472];     // 32*1536*1536 (holds rel after banded gemm)
__device__ half   g_aoh[BT * HDV];        // flash output fp16

// ============================================================
// helpers
// ============================================================
__device__ __forceinline__ uint32_t smem_u32(const void* p) {
    uint32_t a;
    asm("{ .reg .u64 t; cvta.to.shared.u64 t, %1; cvt.u32.u64 %0, t; }" : "=r"(a) : "l"(p));
    return a;
}
__device__ __forceinline__ void cp16(uint32_t s, const void* g) {
    asm volatile("cp.async.ca.shared.global [%0], [%1], 16;" :: "r"(s), "l"(g));
}
#define CP_COMMIT() asm volatile("cp.async.commit_group;" ::: "memory")
#define CP_WAIT(n)  asm volatile("cp.async.wait_group %0;" :: "n"(n) : "memory")

#define LDSM4(r, addr) \
    asm volatile("ldmatrix.sync.aligned.m8n8.x4.shared.b16 {%0,%1,%2,%3}, [%4];" \
        : "=r"((r)[0]), "=r"((r)[1]), "=r"((r)[2]), "=r"((r)[3]) : "r"(addr))

#define MMA(acc, a, b) \
    asm volatile("mma.sync.aligned.m16n8k16.row.col.f32.f16.f16.f32 " \
        "{%0,%1,%2,%3},{%4,%5,%6,%7},{%8,%9},{%0,%1,%2,%3};" \
        : "+f"((acc)[0]), "+f"((acc)[1]), "+f"((acc)[2]), "+f"((acc)[3]) \
        : "r"((a)[0]), "r"((a)[1]), "r"((a)[2]), "r"((a)[3]), "r"((b)[0]), "r"((b)[1]))

#define STS32(addr, v) \
    asm volatile("st.shared.b32 [%0], %1;" :: "r"(addr), "r"(v))

// ---------------- positional basis ----------------
// O(1) gamma max: log-pdf strictly concave in pos>0; integer-grid max at
// floor/ceil of the mode (c-1)/r. Bit-identical to the full scan.
__global__ void gamma_max_kernel(double* gmax) {
    int j = threadIdx.x;
    if (j >= 32) return;
    double conc  = 4.0 * (j + 1) * (j + 1);
    double rate  = (double)(j + 1) / 12.0;
    double lnorm = lgamma(conc) - conc * log(rate);
    double mode = (conc - 1.0) / rate;
    long mlo = (long)floor(mode), mhi = mlo + 1;
    if (mlo < 1) mlo = 1;
    if (mlo > 1535) mlo = 1535;
    if (mhi < 1) mhi = 1;
    if (mhi > 1535) mhi = 1535;
    double best = 0.0;
    for (int k = 0; k < 2; k++) {
        double pos = (double)(k == 0 ? mlo : mhi);
        double pr = exp((conc - 1.0) * log(pos) - rate * pos - lnorm);
        if (pr > best) best = pr;
    }
    gmax[j] = best + 1e-8;
}

__global__ void pe_kernel(const double* __restrict__ gmax, float* __restrict__ pe) {
    int idx = blockIdx.x * blockDim.x + threadIdx.x;
    if (idx >= Ln * 32) return;
    int i = idx / 32, j = idx % 32;
    int dist = i - (Tn - 1);
    double pos = fabs((double)dist);
    double mr = log2((double)Tn);
    double hl = exp2(3.0 + (double)j * (mr - 3.0) / 31.0);
    double fe = exp2(-pos / hl);
    double width = exp2((double)(j + 1)) - 1.0;
    double fc = (width > pos) ? 1.0 : 0.0;
    double conc  = 4.0 * (j + 1) * (j + 1);
    double rate  = (double)(j + 1) / 12.0;
    double lnorm = lgamma(conc) - conc * log(rate);
    double pr = exp((conc - 1.0) * log(pos) - rate * pos - lnorm) + 1e-8;
    double fg = pr / gmax[j];
    float sgn = (dist > 0) ? 1.f : ((dist < 0) ? -1.f : 0.f);
    float* row = pe + (size_t)i * 192;
    row[j]       = (float)fe;
    row[32 + j]  = (float)fc;
    row[64 + j]  = (float)fg;
    row[96 + j]  = sgn * (float)fe;
    row[128 + j] = sgn * (float)fc;
    row[160 + j] = sgn * (float)fg;
}

// ---------------- small fp32 sgemm (rK only) ----------------
__global__ void sgemm_kernel(const float* __restrict__ A, int lda,
                             const float* __restrict__ B, int ldb,
                             float* __restrict__ C, int ldc,
                             int M, int N, int K) {
    __shared__ float As[16][68];
    __shared__ float Bs[16][68];
    int t  = threadIdx.x;
    int tx = t & 15, ty = t >> 4;
    int m0 = blockIdx.y * 64, n0 = blockIdx.x * 64;
    int ar = t >> 2, ac = (t & 3) * 4;
    int br = t >> 4, bc = (t & 15) * 4;
    float s[4][4] = {};
    for (int k0 = 0; k0 < K; k0 += 16) {
        float4 av = make_float4(0.f, 0.f, 0.f, 0.f);
        if (m0 + ar < M)
            av = *(const float4*)(A + (size_t)(m0 + ar) * lda + k0 + ac);
        float4 bv = *(const float4*)(B + (size_t)(k0 + br) * ldb + n0 + bc);
        __syncthreads();
        As[ac + 0][ar] = av.x; As[ac + 1][ar] = av.y;
        As[ac + 2][ar] = av.z; As[ac + 3][ar] = av.w;
        *(float4*)&Bs[br][bc] = bv;
        __syncthreads();
#pragma unroll
        for (int kk = 0; kk < 16; kk++) {
            float4 a = *(const float4*)&As[kk][ty * 4];
            float4 b = *(const float4*)&Bs[kk][tx * 4];
            s[0][0] += a.x * b.x; s[0][1] += a.x * b.y; s[0][2] += a.x * b.z; s[0][3] += a.x * b.w;
            s[1][0] += a.y * b.x; s[1][1] += a.y * b.y; s[1][2] += a.y * b.z; s[1][3] += a.y * b.w;
            s[2][0] += a.z * b.x; s[2][1] += a.z * b.y; s[2][2] += a.z * b.z; s[2][3] += a.z * b.w;
            s[3][0] += a.w * b.x; s[3][1] += a.w * b.y; s[3][2] += a.w * b.z; s[3][3] += a.w * b.w;
        }
    }
#pragma unroll
    for (int i = 0; i < 4; i++) {
        int m = m0 + ty * 4 + i;
        if (m < M) {
            float* cp = C + (size_t)m * ldc + n0 + tx * 4;
#pragma unroll
            for (int j = 0; j < 4; j++) cp[j] = s[i][j];
        }
    }
}

// ---------------- bR bias table: bR[h][l] = (r_r - r_w)[h] . rK[l,h] (fp32 exact) ----------------
__global__ void br_kernel(const float* __restrict__ rK, const float* __restrict__ rwb,
                          const float* __restrict__ rrb, float* __restrict__ bR) {
    int i = blockIdx.x * 256 + threadIdx.x;
    if (i >= Hn * Lp) return;
    int l = i % Lp, h = i / Lp;
    float s = 0.f;
    if (l < Ln) {
        const float* rp = rK + (long)l * HDK + h * DKn;
        const float* wp = rwb + h * DKn;
        const float* qp = rrb + h * DKn;
#pragma unroll
        for (int d = 0; d < DKn; d++) s += (qp[d] - wp[d]) * rp[d];
    }
    bR[i] = s;
}

// ---------------- hi/lo split helpers (fp16) ----------------
__device__ __forceinline__ void split_h(float v, half* hi, half* lo, long o) {
    half h = __float2half_rn(v);
    hi[o] = h;
    lo[o] = __float2half_rn(v - __half2float(h));
}

// vectorized split: 4 floats per thread
__global__ void split_kernel(const float4* __restrict__ src, uint2* __restrict__ hi,
                             uint2* __restrict__ lo, int n4) {
    int i = blockIdx.x * 256 + threadIdx.x;
    if (i >= n4) return;
    float4 v = src[i];
    half h0 = __float2half_rn(v.x), h1 = __float2half_rn(v.y);
    half h2 = __float2half_rn(v.z), h3 = __float2half_rn(v.w);
    half2 hA = __halves2half2(h0, h1), hB = __halves2half2(h2, h3);
    half2 lA = __floats2half2_rn(v.x - __half2float(h0), v.y - __half2float(h1));
    half2 lB = __floats2half2_rn(v.z - __half2float(h2), v.w - __half2float(h3));
    uint2 ho, lw;
    ho.x = *(uint32_t*)&hA; ho.y = *(uint32_t*)&hB;
    lw.x = *(uint32_t*)&lA; lw.y = *(uint32_t*)&lB;
    hi[i] = ho;
    lo[i] = lw;
}

__global__ void tsplit_kernel(const float* __restrict__ src, int K, int N,
                              half* __restrict__ hi, half* __restrict__ lo) {
    __shared__ float tile[32][33];
    int n0 = blockIdx.x * 32, k0 = blockIdx.y * 32;
    int tx = threadIdx.x & 31, ty = threadIdx.x >> 5;
#pragma unroll
    for (int i = 0; i < 32; i += 8)
        tile[ty + i][tx] = src[(long)(k0 + ty + i) * N + n0 + tx];
    __syncthreads();
#pragma unroll
    for (int i = 0; i < 32; i += 8) {
        float v = tile[tx][ty + i];
        long o = (long)(n0 + ty + i) * K + k0 + tx;
        split_h(v, hi, lo, o);
    }
}

__global__ void rkt_kernel(const float* __restrict__ rK, half* rkth, half* rktl) {
    long i = (long)blockIdx.x * 256 + threadIdx.x;
    if (i >= (long)Hn * Lp * DKn) return;
    int d = (int)(i & 63);
    int l = (int)((i >> 6) % Lp);
    int h = (int)(i / ((long)Lp * DKn));
    float v = (l < Ln) ? rK[(long)l * HDK + h * DKn + d] : 0.f;
    split_h(v, rkth, rktl, i);
}

__global__ void vt_kernel(const float* __restrict__ Vf, half* vth, half* vtl) {
    __shared__ float tile[32][33];
    int z = blockIdx.z, h = z & 7, b = z >> 3;
    int t0 = blockIdx.x * 32, d0 = blockIdx.y * 32;
    int tx = threadIdx.x & 31, ty = threadIdx.x >> 5;
#pragma unroll
    for (int i = 0; i < 32; i += 8)
        tile[ty + i][tx] = Vf[((long)(b * Tn + t0 + ty + i)) * HDV + h * DVn + d0 + tx];
    __syncthreads();
#pragma unroll
    for (int i = 0; i < 32; i += 8) {
        float v = tile[tx][ty + i];
        long o = ((long)z * DVn + d0 + ty + i) * Tn + t0 + tx;
        split_h(v, vth, vtl, o);
    }
}

// ============================================================
// mma.sync fp16 GEMM (general):
//   NPASS 3: ah.bh+ah.bl+al.bh   NPASS 2: ah.bh+ah.bl (A hi only)
//   MODE 0: fp32 C = scale*acc + bias[col]
//   MODE 2: banded shifted store (rel) + bias[bR: h*Lp + l]
// ============================================================
template <int NPASS, int MODE>
__global__ void __launch_bounds__(256) gemm_mma(
    const half* __restrict__ Ah, const half* __restrict__ Al, int lda, long sA8, long sA1,
    const half* __restrict__ Bh, const half* __restrict__ Bl, int ldb, long sB8, long sB1,
    void* __restrict__ Cv, int ldc, long sC8, long sC1,
    int Kdim, int Ncols, float scale, const float* __restrict__ bias)
{
    constexpr int NA = (NPASS == 3) ? 2 : 1;
    constexpr int TILEA = 128 * 80;
    constexpr int TILEB = 128 * 80;
    constexpr int STAGE = NA * TILEA + 2 * TILEB;

    extern __shared__ char smem[];
    uint32_t sb = smem_u32(smem);
    int tid = threadIdx.x, lane = tid & 31, wid = tid >> 5;
    int wm = wid >> 2, wn = wid & 3;
    int z = blockIdx.z;
    int m0 = blockIdx.y * 128, n0 = blockIdx.x * 128;

    long zo_a = (long)(z >> 3) * sA8 + (long)(z & 7) * sA1;
    long zo_b = (long)(z >> 3) * sB8 + (long)(z & 7) * sB1;
    long zo_c = (long)(z >> 3) * sC8 + (long)(z & 7) * sC1;
    const half* pAh = Ah + zo_a + (long)m0 * lda;
    const half* pAl = Al + zo_a + (long)m0 * lda;
    long boff = (MODE == 2) ? (long)(Tn - 128 - m0 + n0) : (long)n0;
    const half* pBh = Bh + zo_b + boff * ldb;
    const half* pBl = Bl + zo_b + boff * ldb;

    float acc[4][4][4] = {};
    const int NC = Kdim >> 5;

    auto prefetch = [&](int kc) {
        int k0 = kc * 32;
        uint32_t s0 = sb + (kc & 1) * STAGE;
        for (int i = tid; i < 512; i += 256) {
            int r = i >> 2, c = i & 3;
            uint32_t so = (uint32_t)(r * 80 + c * 16);
            long go = (long)r * lda + k0 + c * 8;
            cp16(s0 + so, pAh + go);
            if (NPASS == 3) cp16(s0 + TILEA + so, pAl + go);
            long gb = (long)r * ldb + k0 + c * 8;
            cp16(s0 + NA * TILEA + so,         pBh + gb);
            cp16(s0 + NA * TILEA + TILEB + so, pBl + gb);
        }
        CP_COMMIT();
    };

    prefetch(0);
    for (int kc = 0; kc < NC; kc++) {
        CP_WAIT(0);
        __syncthreads();
        if (kc + 1 < NC) prefetch(kc + 1);
        uint32_t s0 = sb + (kc & 1) * STAGE;

#pragma unroll
        for (int kk = 0; kk < 2; kk++) {
            int k16 = kk * 16;
            uint32_t ah[4][4], al4[4][4], bh[4][2], bl4[4][2];
            uint32_t arow = (uint32_t)(wm * 64 + (lane & 15));
            uint32_t acol = (uint32_t)(k16 + (lane >> 4) * 8);
#pragma unroll
            for (int mi = 0; mi < 4; mi++) {
                uint32_t ao = s0 + (arow + mi * 16) * 80 + acol * 2;
                LDSM4(ah[mi], ao);
                if (NPASS == 3) LDSM4(al4[mi], ao + TILEA);
            }
            uint32_t brow = (uint32_t)(wn * 32 + (lane & 7) + ((lane >> 4) & 1) * 8);
            uint32_t bcol = (uint32_t)(k16 + ((lane >> 3) & 1) * 8);
#pragma unroll
            for (int g = 0; g < 2; g++) {
                uint32_t t4[4];
                uint32_t bo = s0 + NA * TILEA + (brow + g * 16) * 80 + bcol * 2;
                LDSM4(t4, bo);
                bh[g * 2][0] = t4[0]; bh[g * 2][1] = t4[1];
                bh[g * 2 + 1][0] = t4[2]; bh[g * 2 + 1][1] = t4[3];
                LDSM4(t4, bo + TILEB);
                bl4[g * 2][0] = t4[0]; bl4[g * 2][1] = t4[1];
                bl4[g * 2 + 1][0] = t4[2]; bl4[g * 2 + 1][1] = t4[3];
            }
#pragma unroll
            for (int mi = 0; mi < 4; mi++)
#pragma unroll
                for (int ni = 0; ni < 4; ni++) {
                    MMA(acc[mi][ni], ah[mi], bh[ni]);
                    MMA(acc[mi][ni], ah[mi], bl4[ni]);
                    if (NPASS == 3) MMA(acc[mi][ni], al4[mi], bh[ni]);
                }
        }
        __syncthreads();
    }

    int gID = lane >> 2, tig = lane & 3;
#pragma unroll
    for (int mi = 0; mi < 4; mi++) {
#pragma unroll
        for (int ni = 0; ni < 4; ni++) {
            int rloc = wm * 64 + mi * 16 + gID;
            int coll = wn * 32 + ni * 8 + tig * 2;
            int row0 = m0 + rloc;
            int col  = n0 + coll;
            if (MODE == 0) {
                float* Cf = (float*)Cv;
                if (col < Ncols) {
                    float b0 = bias ? bias[col] : 0.f;
                    float b1 = bias ? bias[col + 1] : 0.f;
                    float* p0 = Cf + zo_c + (long)row0 * ldc + col;
                    float* p1 = Cf + zo_c + (long)(row0 + 8) * ldc + col;
                    *(float2*)p0 = make_float2(acc[mi][ni][0] * scale + b0, acc[mi][ni][1] * scale + b1);
                    *(float2*)p1 = make_float2(acc[mi][ni][2] * scale + b0, acc[mi][ni][3] * scale + b1);
                }
            } else {
                float* Cf = (float*)Cv;
                int lidx = (int)boff + coll;                 // l index (0..Lp-1)
                float bb0 = bias[(z & 7) * Lp + lidx];
                float bb1 = bias[(z & 7) * Lp + lidx + 1];
                int k0a = n0 + coll + rloc - 127;
                int k0b = k0a + 8;
                float* r0p = Cf + zo_c + (long)row0 * ldc;
                float* r1p = r0p + 8L * ldc;
                if (k0a >= 0     && k0a < Tn)     r0p[k0a]     = acc[mi][ni][0] + bb0;
                if (k0a + 1 >= 0 && k0a + 1 < Tn) r0p[k0a + 1] = acc[mi][ni][1] + bb1;
                if (k0b >= 0     && k0b < Tn)     r1p[k0b]     = acc[mi][ni][2] + bb0;
                if (k0b + 1 >= 0 && k0b + 1 < Tn) r1p[k0b + 1] = acc[mi][ni][3] + bb1;
            }
        }
    }
}

// ============================================================
// fused Q+K projection: epilogue writes qw (Q+r_w, scaled) and K only
// (rel reuses qw; the r_r-r_w part is folded into the bR bias table)
// ============================================================
__global__ void __launch_bounds__(256) qkproj_kernel(
    const half* __restrict__ Ah, const half* __restrict__ Al,
    const half* __restrict__ Bh, const half* __restrict__ Bl,
    const float* __restrict__ rwb,
    half* __restrict__ qwh, half* __restrict__ qwl,
    half* __restrict__ kh,  half* __restrict__ kl)
{
    constexpr int TILEA = 128 * 80;
    constexpr int TILEB = 128 * 80;
    constexpr int STAGE = 2 * TILEA + 2 * TILEB;

    extern __shared__ char smem[];
    uint32_t sb = smem_u32(smem);
    int tid = threadIdx.x, lane = tid & 31, wid = tid >> 5;
    int wm = wid >> 2, wn = wid & 3;
    int m0 = blockIdx.y * 128, n0 = blockIdx.x * 128;
    int bIdx = m0 / Tn, t0 = m0 % Tn;

    const half* pAh = Ah + (long)m0 * Cin;
    const half* pAl = Al + (long)m0 * Cin;
    const half* pBh = Bh + (long)n0 * Cin;
    const half* pBl = Bl + (long)n0 * Cin;

    float acc[4][4][4] = {};
    const int NC = Cin >> 5;

    auto prefetch = [&](int kc) {
        int k0 = kc * 32;
        uint32_t s0 = sb + (kc & 1) * STAGE;
        for (int i = tid; i < 512; i += 256) {
            int r = i >> 2, c = i & 3;
            uint32_t so = (uint32_t)(r * 80 + c * 16);
            long go = (long)r * Cin + k0 + c * 8;
            cp16(s0 + so,         pAh + go);
            cp16(s0 + TILEA + so, pAl + go);
            cp16(s0 + 2 * TILEA + so,         pBh + go);
            cp16(s0 + 2 * TILEA + TILEB + so, pBl + go);
        }
        CP_COMMIT();
    };

    prefetch(0);
    for (int kc = 0; kc < NC; kc++) {
        CP_WAIT(0);
        __syncthreads();
        if (kc + 1 < NC) prefetch(kc + 1);
        uint32_t s0 = sb + (kc & 1) * STAGE;

#pragma unroll
        for (int kk = 0; kk < 2; kk++) {
            int k16 = kk * 16;
            uint32_t ah[4][4], al4[4][4], bh[4][2], bl4[4][2];
            uint32_t arow = (uint32_t)(wm * 64 + (lane & 15));
            uint32_t acol = (uint32_t)(k16 + (lane >> 4) * 8);
#pragma unroll
            for (int mi = 0; mi < 4; mi++) {
                uint32_t ao = s0 + (arow + mi * 16) * 80 + acol * 2;
                LDSM4(ah[mi], ao);
                LDSM4(al4[mi], ao + TILEA);
            }
            uint32_t brow = (uint32_t)(wn * 32 + (lane & 7) + ((lane >> 4) & 1) * 8);
            uint32_t bcol = (uint32_t)(k16 + ((lane >> 3) & 1) * 8);
#pragma unroll
            for (int g = 0; g < 2; g++) {
                uint32_t t4[4];
                uint32_t bo = s0 + 2 * TILEA + (brow + g * 16) * 80 + bcol * 2;
                LDSM4(t4, bo);
                bh[g * 2][0] = t4[0]; bh[g * 2][1] = t4[1];
                bh[g * 2 + 1][0] = t4[2]; bh[g * 2 + 1][1] = t4[3];
                LDSM4(t4, bo + TILEB);
                bl4[g * 2][0] = t4[0]; bl4[g * 2][1] = t4[1];
                bl4[g * 2 + 1][0] = t4[2]; bl4[g * 2 + 1][1] = t4[3];
            }
#pragma unroll
            for (int mi = 0; mi < 4; mi++)
#pragma unroll
                for (int ni = 0; ni < 4; ni++) {
                    MMA(acc[mi][ni], ah[mi], bh[ni]);
                    MMA(acc[mi][ni], ah[mi], bl4[ni]);
                    MMA(acc[mi][ni], al4[mi], bh[ni]);
                }
        }
        __syncthreads();
    }

    int gID = lane >> 2, tig = lane & 3;
#pragma unroll
    for (int mi = 0; mi < 4; mi++) {
#pragma unroll
        for (int ni = 0; ni < 4; ni++) {
            int rloc = wm * 64 + mi * 16 + gID;
            int coll = wn * 32 + ni * 8 + tig * 2;
            int col  = n0 + coll;
#pragma unroll
            for (int half_i = 0; half_i < 2; half_i++) {
                int t = t0 + rloc + half_i * 8;
                float v0 = acc[mi][ni][half_i * 2 + 0];
                float v1 = acc[mi][ni][half_i * 2 + 1];
                if (col < 512) {
                    int h = col >> 6, d = col & 63;
                    long o = ((long)(bIdx * 8 + h) * Tn + t) * 64 + d;
                    float w0 = v0 * 0.125f + rwb[col], w1 = v1 * 0.125f + rwb[col + 1];
                    half wh0 = __float2half_rn(w0), wh1 = __float2half_rn(w1);
                    *(half2*)(qwh + o) = __halves2half2(wh0, wh1);
                    *(half2*)(qwl + o) = __floats2half2_rn(w0 - __half2float(wh0), w1 - __half2float(wh1));
                } else {
                    int ck = col - 512;
                    int h = ck >> 6, d = ck & 63;
                    long o = ((long)(bIdx * 8 + h) * Tn + t) * 64 + d;
                    half kh0 = __float2half_rn(v0), kh1 = __float2half_rn(v1);
                    *(half2*)(kh + o) = __halves2half2(kh0, kh1);
                    *(half2*)(kl + o) = __floats2half2_rn(v0 - __half2float(kh0), v1 - __half2float(kh1));
                }
            }
        }
    }
}

// ============================================================
// flash kernel (R8 winner: S 3-pass, PV 2-pass; 187904B smem — occ-1, no colocation)
// ============================================================
__global__ void __launch_bounds__(256) flash_kernel(
    const half* __restrict__ qwh_, const half* __restrict__ qwl_,
    const half* __restrict__ kh_,  const half* __restrict__ kl_,
    const half* __restrict__ vth_, const half* __restrict__ vtl_,
    const float* __restrict__ logits, half* __restrict__ aoh, int z0)
{
    extern __shared__ char smem[];
    uint32_t sb = smem_u32(smem);
    const uint32_t QB = sb, KB = sb + 40960, PB = sb + 81920, VB = sb + 122880;
    float* mArr = (float*)(smem + 184320);
    float* lArr = mArr + 128;
    float* aArr = lArr + 128;
    float* red  = aArr + 128;   // [128][4]

    int tid = threadIdx.x, lane = tid & 31, wid = tid >> 5;
    int wm = wid >> 2, wn = wid & 3;
    int wm2 = wid >> 1, wn2 = wid & 1;
    int gID = lane >> 2, tig = lane & 3;
    int z = blockIdx.z + z0;
    int q0 = blockIdx.y * 128;
    int h = z & 7, b = z >> 3;

    long zq = (long)z * Tn * DKn;
    const half* pQh = qwh_ + zq + (long)q0 * DKn;
    const half* pQl = qwl_ + zq + (long)q0 * DKn;
    const half* pKh = kh_ + zq;
    const half* pKl = kl_ + zq;
    long zv = (long)z * DVn * Tn;
    const float* pL = logits + (long)z * Tn * Tn + (long)q0 * Tn;

    for (int r = tid; r < 128; r += 256) { mArr[r] = -1e30f; lArr[r] = 0.f; }

    for (int i = tid; i < 1024; i += 256) {
        int r = i >> 3, c = i & 7;
        uint32_t off = (uint32_t)((c >> 2) * 10240 + r * 80 + (c & 3) * 16);
        cp16(QB + off,         pQh + (long)r * DKn + c * 8);
        cp16(QB + 20480 + off, pQl + (long)r * DKn + c * 8);
        cp16(KB + off,         pKh + (long)r * DKn + c * 8);
        cp16(KB + 20480 + off, pKl + (long)r * DKn + c * 8);
    }
    CP_COMMIT();

    float O[2][12][4] = {};

    auto loadK = [&](int kn) {
        const half* gh = pKh + (long)kn * 128 * DKn;
        const half* gl = pKl + (long)kn * 128 * DKn;
        for (int i = tid; i < 1024; i += 256) {
            int r = i >> 3, c = i & 7;
            uint32_t off = (uint32_t)((c >> 2) * 10240 + r * 80 + (c & 3) * 16);
            cp16(KB + off,         gh + (long)r * DKn + c * 8);
            cp16(KB + 20480 + off, gl + (long)r * DKn + c * 8);
        }
        CP_COMMIT();
    };

    for (int kt = 0; kt < 12; kt++) {
        CP_WAIT(0);
        __syncthreads();

        float S[4][4][4] = {};
#pragma unroll
        for (int chunk = 0; chunk < 2; chunk++) {
            uint32_t qbase = QB + chunk * 10240;
            uint32_t kbase = KB + chunk * 10240;
#pragma unroll
            for (int kk = 0; kk < 2; kk++) {
                int k16 = kk * 16;
                uint32_t ah[4][4], al4[4][4], bh[4][2], bl4[4][2];
                uint32_t arow = (uint32_t)(wm * 64 + (lane & 15));
                uint32_t acol = (uint32_t)(k16 + (lane >> 4) * 8);
#pragma unroll
                for (int mi = 0; mi < 4; mi++) {
                    uint32_t ao = qbase + (arow + mi * 16) * 80 + acol * 2;
                    LDSM4(ah[mi], ao);
                    LDSM4(al4[mi], ao + 20480);
                }
                uint32_t brow = (uint32_t)(wn * 32 + (lane & 7) + ((lane >> 4) & 1) * 8);
                uint32_t bcol = (uint32_t)(k16 + ((lane >> 3) & 1) * 8);
#pragma unroll
                for (int g = 0; g < 2; g++) {
                    uint32_t t4[4];
                    uint32_t bo = kbase + (brow + g * 16) * 80 + bcol * 2;
                    LDSM4(t4, bo);
                    bh[g * 2][0] = t4[0]; bh[g * 2][1] = t4[1];
                    bh[g * 2 + 1][0] = t4[2]; bh[g * 2 + 1][1] = t4[3];
                    LDSM4(t4, bo + 20480);
                    bl4[g * 2][0] = t4[0]; bl4[g * 2][1] = t4[1];
                    bl4[g * 2 + 1][0] = t4[2]; bl4[g * 2 + 1][1] = t4[3];
                }
#pragma unroll
                for (int mi = 0; mi < 4; mi++)
#pragma unroll
                    for (int ni = 0; ni < 4; ni++) {
                        MMA(S[mi][ni], ah[mi], bh[ni]);
                        MMA(S[mi][ni], ah[mi], bl4[ni]);
                        MMA(S[mi][ni], al4[mi], bh[ni]);
                    }
            }
        }

#pragma unroll
        for (int mi = 0; mi < 4; mi++) {
            int r0 = wm * 64 + mi * 16 + gID;
#pragma unroll
            for (int ni = 0; ni < 4; ni++) {
                long coff = (long)kt * 128 + wn * 32 + ni * 8 + tig * 2;
                float2 v0 = *(const float2*)(pL + (long)r0 * Tn + coff);
                float2 v1 = *(const float2*)(pL + (long)(r0 + 8) * Tn + coff);
                S[mi][ni][0] += v0.x; S[mi][ni][1] += v0.y;
                S[mi][ni][2] += v1.x; S[mi][ni][3] += v1.y;
            }
        }

#pragma unroll
        for (int mi = 0; mi < 4; mi++) {
            float m0v = -1e30f, m1v = -1e30f;
#pragma unroll
            for (int ni = 0; ni < 4; ni++) {
                m0v = fmaxf(m0v, fmaxf(S[mi][ni][0], S[mi][ni][1]));
                m1v = fmaxf(m1v, fmaxf(S[mi][ni][2], S[mi][ni][3]));
            }
            m0v = fmaxf(m0v, __shfl_xor_sync(0xffffffffu, m0v, 1));
            m0v = fmaxf(m0v, __shfl_xor_sync(0xffffffffu, m0v, 2));
            m1v = fmaxf(m1v, __shfl_xor_sync(0xffffffffu, m1v, 1));
            m1v = fmaxf(m1v, __shfl_xor_sync(0xffffffffu, m1v, 2));
            if (tig == 0) {
                int r0 = wm * 64 + mi * 16 + gID;
                red[r0 * 4 + wn] = m0v;
                red[(r0 + 8) * 4 + wn] = m1v;
            }
        }
        __syncthreads();

        float mns0[4], mns1[4], alp0[4], alp1[4], sum0[4], sum1[4];
#pragma unroll
        for (int mi = 0; mi < 4; mi++) {
            int r0 = wm * 64 + mi * 16 + gID, r1 = r0 + 8;
            float mo0 = mArr[r0], mo1 = mArr[r1];
            float mn0 = mo0, mn1 = mo1;
#pragma unroll
            for (int w = 0; w < 4; w++) {
                mn0 = fmaxf(mn0, red[r0 * 4 + w]);
                mn1 = fmaxf(mn1, red[r1 * 4 + w]);
            }
            float s0 = 0.f, s1 = 0.f;
#pragma unroll
            for (int ni = 0; ni < 4; ni++) {
                S[mi][ni][0] = __expf(S[mi][ni][0] - mn0);
                S[mi][ni][1] = __expf(S[mi][ni][1] - mn0);
                S[mi][ni][2] = __expf(S[mi][ni][2] - mn1);
                S[mi][ni][3] = __expf(S[mi][ni][3] - mn1);
                s0 += S[mi][ni][0] + S[mi][ni][1];
                s1 += S[mi][ni][2] + S[mi][ni][3];
            }
            s0 += __shfl_xor_sync(0xffffffffu, s0, 1);
            s0 += __shfl_xor_sync(0xffffffffu, s0, 2);
            s1 += __shfl_xor_sync(0xffffffffu, s1, 1);
            s1 += __shfl_xor_sync(0xffffffffu, s1, 2);
            mns0[mi] = mn0; mns1[mi] = mn1;
            alp0[mi] = __expf(mo0 - mn0); alp1[mi] = __expf(mo1 - mn1);
            sum0[mi] = s0; sum1[mi] = s1;
        }
        __syncthreads();

#pragma unroll
        for (int mi = 0; mi < 4; mi++) {
            int r0 = wm * 64 + mi * 16 + gID, r1 = r0 + 8;
            if (tig == 0) {
                red[r0 * 4 + wn] = sum0[mi];
                red[r1 * 4 + wn] = sum1[mi];
                if (wn == 0) { aArr[r0] = alp0[mi]; aArr[r1] = alp1[mi]; }
            }
#pragma unroll
            for (int ni = 0; ni < 4; ni++) {
                int colin = ni * 8 + tig * 2;
                half2 h0 = __floats2half2_rn(S[mi][ni][0], S[mi][ni][1]);
                half2 h1 = __floats2half2_rn(S[mi][ni][2], S[mi][ni][3]);
                uint32_t p0 = PB + wn * 10240 + r0 * 80 + colin * 2;
                uint32_t p1 = PB + wn * 10240 + r1 * 80 + colin * 2;
                STS32(p0, *(uint32_t*)&h0);
                STS32(p1, *(uint32_t*)&h1);
            }
        }
        __syncthreads();

        if (wn == 0 && tig == 0) {
#pragma unroll
            for (int mi = 0; mi < 4; mi++) {
                int r0 = wm * 64 + mi * 16 + gID, r1 = r0 + 8;
                lArr[r0] = lArr[r0] * alp0[mi] + red[r0 * 4 + 0] + red[r0 * 4 + 1] + red[r0 * 4 + 2] + red[r0 * 4 + 3];
                lArr[r1] = lArr[r1] * alp1[mi] + red[r1 * 4 + 0] + red[r1 * 4 + 1] + red[r1 * 4 + 2] + red[r1 * 4 + 3];
                mArr[r0] = mns0[mi];
                mArr[r1] = mns1[mi];
            }
        }

        {
            const half* gh = vth_ + zv + (long)kt * 128;
            const half* gl = vtl_ + zv + (long)kt * 128;
            for (int cc2 = 0; cc2 < 2; cc2++) {
                uint32_t vb = VB + cc2 * 30720;
                for (int i = tid; i < 768; i += 256) {
                    int r = i >> 2, c4 = i & 3;
                    uint32_t off = (uint32_t)(r * 80 + c4 * 16);
                    cp16(vb + off,         gh + (long)r * Tn + cc2 * 32 + c4 * 8);
                    cp16(vb + 15360 + off, gl + (long)r * Tn + cc2 * 32 + c4 * 8);
                }
                CP_COMMIT();
            }
            loadK((kt + 1 < 12) ? kt + 1 : 11);
        }

#pragma unroll
        for (int mi = 0; mi < 2; mi++) {
            float a0 = aArr[wm2 * 32 + mi * 16 + gID];
            float a1 = aArr[wm2 * 32 + mi * 16 + gID + 8];
#pragma unroll
            for (int ni = 0; ni < 12; ni++) {
                O[mi][ni][0] *= a0; O[mi][ni][1] *= a0;
                O[mi][ni][2] *= a1; O[mi][ni][3] *= a1;
            }
        }

        auto pvChunk = [&](int c) {
            uint32_t pb = PB + c * 10240;
            uint32_t vb = VB + (c & 1) * 30720;
#pragma unroll
            for (int kk = 0; kk < 2; kk++) {
                int k16 = kk * 16;
                uint32_t pa[2][4], vh[12][2], vl[12][2];
                uint32_t arow = (uint32_t)(wm2 * 32 + (lane & 15));
                uint32_t acol = (uint32_t)(k16 + (lane >> 4) * 8);
#pragma unroll
                for (int mi = 0; mi < 2; mi++)
                    LDSM4(pa[mi], pb + (arow + mi * 16) * 80 + acol * 2);
                uint32_t brow = (uint32_t)(wn2 * 96 + (lane & 7) + ((lane >> 4) & 1) * 8);
                uint32_t bcol = (uint32_t)(k16 + ((lane >> 3) & 1) * 8);
#pragma unroll
                for (int g = 0; g < 6; g++) {
                    uint32_t t4[4];
                    uint32_t bo = vb + (brow + g * 16) * 80 + bcol * 2;
                    LDSM4(t4, bo);
                    vh[g * 2][0] = t4[0]; vh[g * 2][1] = t4[1];
                    vh[g * 2 + 1][0] = t4[2]; vh[g * 2 + 1][1] = t4[3];
                    LDSM4(t4, bo + 15360);
                    vl[g * 2][0] = t4[0]; vl[g * 2][1] = t4[1];
                    vl[g * 2 + 1][0] = t4[2]; vl[g * 2 + 1][1] = t4[3];
                }
#pragma unroll
                for (int mi = 0; mi < 2; mi++)
#pragma unroll
                    for (int ni = 0; ni < 12; ni++) {
                        MMA(O[mi][ni], pa[mi], vh[ni]);
                        MMA(O[mi][ni], pa[mi], vl[ni]);
                    }
            }
        };
        auto loadV = [&](int c) {
            uint32_t vb = VB + (c & 1) * 30720;
            const half* gh = vth_ + zv + (long)kt * 128 + c * 32;
            const half* gl = vtl_ + zv + (long)kt * 128 + c * 32;
            for (int i = tid; i < 768; i += 256) {
                int r = i >> 2, c4 = i & 3;
                uint32_t off = (uint32_t)(r * 80 + c4 * 16);
                cp16(vb + off,         gh + (long)r * Tn + c4 * 8);
                cp16(vb + 15360 + off, gl + (long)r * Tn + c4 * 8);
            }
            CP_COMMIT();
        };

        CP_WAIT(2); __syncthreads();
        pvChunk(0);
        __syncthreads(); loadV(2);
        CP_WAIT(2); __syncthreads();
        pvChunk(1);
        __syncthreads(); loadV(3);
        CP_WAIT(1); __syncthreads();
        pvChunk(2);
        CP_WAIT(0); __syncthreads();
        pvChunk(3);
    }

    __syncthreads();
#pragma unroll
    for (int mi = 0; mi < 2; mi++) {
        int rl0 = wm2 * 32 + mi * 16 + gID, rl1 = rl0 + 8;
        float i0 = 1.f / lArr[rl0], i1 = 1.f / lArr[rl1];
        long base0 = ((long)(b * Tn + q0 + rl0)) * HDV + h * 192;
        long base1 = ((long)(b * Tn + q0 + rl1)) * HDV + h * 192;
#pragma unroll
        for (int ni = 0; ni < 12; ni++) {
            int col = wn2 * 96 + ni * 8 + tig * 2;
            *(half2*)(aoh + base0 + col) = __floats2half2_rn(O[mi][ni][0] * i0, O[mi][ni][1] * i0);
            *(half2*)(aoh + base1 + col) = __floats2half2_rn(O[mi][ni][2] * i1, O[mi][ni][3] * i1);
        }
    }
}

// ---------------- launch: R8 exact DAG + bR bias table ----------------
extern "C" void kernel_launch(void* const* d_in, const int* in_sizes, int n_in,
                              void* d_out, int out_size) {
    const float* x       = (const float*)d_in[0];
    const float* W_q     = (const float*)d_in[1];
    const float* W_k     = (const float*)d_in[2];
    const float* W_v     = (const float*)d_in[3];
    const float* W_rel_k = (const float*)d_in[4];
    const float* W_out   = (const float*)d_in[5];
    const float* b_out   = (const float*)d_in[6];
    const float* rwb     = (const float*)d_in[7];
    const float* rrb     = (const float*)d_in[8];
    float* out = (float*)d_out;

    float *pe, *rK, *Vf, *logits, *bR;
    double* gmax;
    half *xh, *xl, *wqkh, *wqkl, *wvth, *wvtl, *woth, *wotl;
    half *qwh, *qwl, *kh, *kl, *rkth, *rktl, *vth, *vtl, *aoh;
    cudaGetSymbolAddress((void**)&pe, g_pe);
    cudaGetSymbolAddress((void**)&rK, g_rK);
    cudaGetSymbolAddress((void**)&gmax, g_gmax);
    cudaGetSymbolAddress((void**)&bR, g_bR);
    cudaGetSymbolAddress((void**)&Vf, g_Vf);
    cudaGetSymbolAddress((void**)&xh, g_xh);   cudaGetSymbolAddress((void**)&xl, g_xl);
    cudaGetSymbolAddress((void**)&wqkh, g_wqkh); cudaGetSymbolAddress((void**)&wqkl, g_wqkl);
    cudaGetSymbolAddress((void**)&wvth, g_wvth); cudaGetSymbolAddress((void**)&wvtl, g_wvtl);
    cudaGetSymbolAddress((void**)&woth, g_woth); cudaGetSymbolAddress((void**)&wotl, g_wotl);
    cudaGetSymbolAddress((void**)&qwh, g_qwh); cudaGetSymbolAddress((void**)&qwl, g_qwl);
    cudaGetSymbolAddress((void**)&kh, g_kh);   cudaGetSymbolAddress((void**)&kl, g_kl);
    cudaGetSymbolAddress((void**)&rkth, g_rkth); cudaGetSymbolAddress((void**)&rktl, g_rktl);
    cudaGetSymbolAddress((void**)&vth, g_vth); cudaGetSymbolAddress((void**)&vtl, g_vtl);
    cudaGetSymbolAddress((void**)&logits, g_logits);
    cudaGetSymbolAddress((void**)&aoh, g_aoh);

    const int SM_3 = 2 * (2 * 128 * 80 + 2 * 128 * 80);  // 81920
    const int SM_2 = 2 * (1 * 128 * 80 + 2 * 128 * 80);  // 61440
    const int SM_F = 187904;

    static bool inited = false;
    static cudaStream_t s1, s2;
    static cudaEvent_t evStart, evX, evRK, evVT, evRel, evD2;
    if (!inited) {
        cudaStreamCreateWithFlags(&s1, cudaStreamNonBlocking);
        cudaStreamCreateWithFlags(&s2, cudaStreamNonBlocking);
        cudaEventCreateWithFlags(&evStart, cudaEventDisableTiming);
        cudaEventCreateWithFlags(&evX, cudaEventDisableTiming);
        cudaEventCreateWithFlags(&evRK, cudaEventDisableTiming);
        cudaEventCreateWithFlags(&evVT, cudaEventDisableTiming);
        cudaEventCreateWithFlags(&evRel, cudaEventDisableTiming);
        cudaEventCreateWithFlags(&evD2, cudaEventDisableTiming);
        cudaFuncSetAttribute(gemm_mma<3, 2>, cudaFuncAttributeMaxDynamicSharedMemorySize, SM_3);
        cudaFuncSetAttribute(gemm_mma<2, 0>, cudaFuncAttributeMaxDynamicSharedMemorySize, SM_2);
        cudaFuncSetAttribute(qkproj_kernel, cudaFuncAttributeMaxDynamicSharedMemorySize, SM_3);
        cudaFuncSetAttribute(flash_kernel, cudaFuncAttributeMaxDynamicSharedMemorySize, SM_F);
        inited = true;
    }

    long sQ = (long)Tn * DKn;
    long sR = (long)Lp * DKn;
    long sL = (long)Tn * Tn;

    // ---- fork ----
    cudaEventRecord(evStart, 0);
    cudaStreamWaitEvent(s1, evStart, 0);
    cudaStreamWaitEvent(s2, evStart, 0);

    // s1: positional basis chain -> rkt + bR table  (hidden behind s0)
    gamma_max_kernel<<<1, 32, 0, s1>>>(gmax);
    pe_kernel<<<(Ln * 32 + 255) / 256, 256, 0, s1>>>(gmax, pe);
    sgemm_kernel<<<dim3(HDK / 64, (Ln + 63) / 64), 256, 0, s1>>>(
        pe, 192, W_rel_k, HDK, rK, HDK, Ln, HDK, 192);
    rkt_kernel<<<(int)(((long)Hn * Lp * DKn + 255) / 256), 256, 0, s1>>>(rK, rkth, rktl);
    br_kernel<<<(Hn * Lp + 255) / 256, 256, 0, s1>>>(rK, rwb, rrb, bR);
    cudaEventRecord(evRK, s1);

    // s2: W_v tsplit (no deps)
    tsplit_kernel<<<dim3(HDV / 32, Cin / 32), 256, 0, s2>>>(W_v, Cin, HDV, wvth, wvtl);

    // s0: x split
    split_kernel<<<(BT * Cin / 4 + 255) / 256, 256>>>(
        (const float4*)x, (uint2*)xh, (uint2*)xl, BT * Cin / 4);
    cudaEventRecord(evX, 0);
    cudaStreamWaitEvent(s2, evX, 0);

    // s2: V projection (2-pass) + head transpose
    gemm_mma<2, 0><<<dim3(HDV / 128, BT / 128, 1), 256, SM_2, s2>>>(
        xh, xh, Cin, 0, 0, wvth, wvtl, Cin, 0, 0, Vf, HDV, 0, 0, Cin, HDV, 1.0f, nullptr);
    vt_kernel<<<dim3(Tn / 32, DVn / 32, NBH), 256, 0, s2>>>(Vf, vth, vtl);
    cudaEventRecord(evVT, s2);

    // s0: weight tsplits + fused QK projection (R8 exact order)
    tsplit_kernel<<<dim3(HDK / 32, Cin / 32), 256>>>(W_q, Cin, HDK, wqkh, wqkl);
    tsplit_kernel<<<dim3(HDK / 32, Cin / 32), 256>>>(W_k, Cin, HDK,
                                                     wqkh + (long)512 * Cin, wqkl + (long)512 * Cin);
    tsplit_kernel<<<dim3(HDV / 32, HDV / 32), 256>>>(W_out, HDV, HDV, woth, wotl);
    qkproj_kernel<<<dim3(1024 / 128, BT / 128, 1), 256, SM_3>>>(
        xh, xl, wqkh, wqkl, rwb, qwh, qwl, kh, kl);

    // s0: rel = (Q+r_w).rK^T + bR[h,l]  (A = qw, bias table) -> logits
    cudaStreamWaitEvent(0, evRK, 0);
    gemm_mma<3, 2><<<dim3(13, Tn / 128, NBH), 256, SM_3>>>(
        qwh, qwl, DKn, 8 * sQ, sQ, rkth, rktl, DKn, 0, sR,
        logits, Tn, 8 * sL, sL, DKn, Tn, 1.0f, bR);
    cudaEventRecord(evRel, 0);

    // s0: flash half 1 -> out-proj b0,b1
    cudaStreamWaitEvent(0, evVT, 0);
    flash_kernel<<<dim3(1, Tn / 128, 16), 256, SM_F>>>(
        qwh, qwl, kh, kl, vth, vtl, logits, aoh, 0);
    gemm_mma<2, 0><<<dim3(HDV / 128, 2 * Tn / 128, 1), 256, SM_2>>>(
        aoh, aoh, HDV, 0, 0, woth, wotl, HDV, 0, 0, out, HDV, 0, 0, HDV, HDV, 1.0f, b_out);

    // s2: flash half 2 -> out-proj b2,b3 (dense with half 1; Wout ordered via evRel)
    cudaStreamWaitEvent(s2, evRel, 0);
    flash_kernel<<<dim3(1, Tn / 128, 16), 256, SM_F, s2>>>(
        qwh, qwl, kh, kl, vth, vtl, logits, aoh, 16);
    gemm_mma<2, 0><<<dim3(HDV / 128, 2 * Tn / 128, 1), 256, SM_2, s2>>>(
        aoh + (long)2 * Tn * HDV, aoh + (long)2 * Tn * HDV, HDV, 0, 0,
        woth, wotl, HDV, 0, 0,
        out + (long)2 * Tn * HDV, HDV, 0, 0, HDV, HDV, 1.0f, b_out);
    cudaEventRecord(evD2, s2);

    // ---- join ----
    cudaStreamWaitEvent(0, evD2, 0);
}

// round 16
// speedup vs baseline: 1.0133x; 1.0133x over previous
#include <cuda_runtime.h>
#include <cuda_fp16.h>
#include <math.h>
#include <stdint.h>

// Problem constants
#define Tn   1536
#define Bn   4
#define Hn   8
#define DKn  64
#define DVn  192
#define Ln   3071          // 2T-1
#define Lp   3072          // padded
#define HDK  512           // H*DK
#define HDV  1536          // H*DV
#define BT   6144          // B*T
#define NBH  32            // B*H
#define Cin  1536

// ---------------- device scratch ----------------
__device__ float  g_pe[Ln * 192];
__device__ float  g_rK[Ln * HDK];
__device__ double g_gmax[32];

__device__ float  g_Vf[BT * HDV];

__device__ half   g_xh[BT * Cin], g_xl[BT * Cin];
__device__ half   g_wqkh[1024 * Cin], g_wqkl[1024 * Cin];   // W_q^T | W_k^T concat
__device__ half   g_wvth[HDV * Cin], g_wvtl[HDV * Cin];
__device__ half   g_woth[HDV * HDV], g_wotl[HDV * HDV];

__device__ half   g_qwh[NBH * Tn * DKn], g_qwl[NBH * Tn * DKn];
__device__ half   g_qrh[NBH * Tn * DKn], g_qrl[NBH * Tn * DKn];
__device__ half   g_kh [NBH * Tn * DKn], g_kl [NBH * Tn * DKn];
__device__ half   g_rkth[Hn * Lp * DKn], g_rktl[Hn * Lp * DKn];
__device__ half   g_vth[NBH * DVn * Tn], g_vtl[NBH * DVn * Tn];

__device__ float  g_logits[75497472];     // 32*1536*1536 (holds rel after banded gemm)
__device__ half   g_aoh[BT * HDV];        // flash output fp16

// ============================================================
// helpers
// ============================================================
__device__ __forceinline__ uint32_t smem_u32(const void* p) {
    uint32_t a;
    asm("{ .reg .u64 t; cvta.to.shared.u64 t, %1; cvt.u32.u64 %0, t; }" : "=r"(a) : "l"(p));
    return a;
}
__device__ __forceinline__ void cp16(uint32_t s, const void* g) {
    asm volatile("cp.async.ca.shared.global [%0], [%1], 16;" :: "r"(s), "l"(g));
}
#define CP_COMMIT() asm volatile("cp.async.commit_group;" ::: "memory")
#define CP_WAIT(n)  asm volatile("cp.async.wait_group %0;" :: "n"(n) : "memory")

#define LDSM4(r, addr) \
    asm volatile("ldmatrix.sync.aligned.m8n8.x4.shared.b16 {%0,%1,%2,%3}, [%4];" \
        : "=r"((r)[0]), "=r"((r)[1]), "=r"((r)[2]), "=r"((r)[3]) : "r"(addr))

#define MMA(acc, a, b) \
    asm volatile("mma.sync.aligned.m16n8k16.row.col.f32.f16.f16.f32 " \
        "{%0,%1,%2,%3},{%4,%5,%6,%7},{%8,%9},{%0,%1,%2,%3};" \
        : "+f"((acc)[0]), "+f"((acc)[1]), "+f"((acc)[2]), "+f"((acc)[3]) \
        : "r"((a)[0]), "r"((a)[1]), "r"((a)[2]), "r"((a)[3]), "r"((b)[0]), "r"((b)[1]))

#define STS32(addr, v) \
    asm volatile("st.shared.b32 [%0], %1;" :: "r"(addr), "r"(v))

// ---------------- positional basis (validated) ----------------
__global__ void gamma_max_kernel(double* gmax) {
    __shared__ double red[256];
    int j = blockIdx.x, t = threadIdx.x;
    double conc  = 4.0 * (j + 1) * (j + 1);
    double rate  = (double)(j + 1) / 12.0;
    double lnorm = lgamma(conc) - conc * log(rate);
    double best = 0.0;
    for (int i = t; i < Ln; i += 256) {
        double pos = fabs((double)(i - (Tn - 1)));
        double lu = (conc - 1.0) * log(pos) - rate * pos;
        double pr = exp(lu - lnorm);
        if (pr > best) best = pr;
    }
    red[t] = best;
    __syncthreads();
    for (int s = 128; s; s >>= 1) {
        if (t < s) red[t] = fmax(red[t], red[t + s]);
        __syncthreads();
    }
    if (t == 0) gmax[j] = red[0] + 1e-8;
}

__global__ void pe_kernel(const double* __restrict__ gmax, float* __restrict__ pe) {
    int idx = blockIdx.x * blockDim.x + threadIdx.x;
    if (idx >= Ln * 32) return;
    int i = idx / 32, j = idx % 32;
    int dist = i - (Tn - 1);
    double pos = fabs((double)dist);
    double mr = log2((double)Tn);
    double hl = exp2(3.0 + (double)j * (mr - 3.0) / 31.0);
    double fe = exp2(-pos / hl);
    double width = exp2((double)(j + 1)) - 1.0;
    double fc = (width > pos) ? 1.0 : 0.0;
    double conc  = 4.0 * (j + 1) * (j + 1);
    double rate  = (double)(j + 1) / 12.0;
    double lnorm = lgamma(conc) - conc * log(rate);
    double pr = exp((conc - 1.0) * log(pos) - rate * pos - lnorm) + 1e-8;
    double fg = pr / gmax[j];
    float sgn = (dist > 0) ? 1.f : ((dist < 0) ? -1.f : 0.f);
    float* row = pe + (size_t)i * 192;
    row[j]       = (float)fe;
    row[32 + j]  = (float)fc;
    row[64 + j]  = (float)fg;
    row[96 + j]  = sgn * (float)fe;
    row[128 + j] = sgn * (float)fc;
    row[160 + j] = sgn * (float)fg;
}

// ---------------- small fp32 sgemm (rK only) ----------------
__global__ void sgemm_kernel(const float* __restrict__ A, int lda,
                             const float* __restrict__ B, int ldb,
                             float* __restrict__ C, int ldc,
                             int M, int N, int K) {
    __shared__ float As[16][68];
    __shared__ float Bs[16][68];
    int t  = threadIdx.x;
    int tx = t & 15, ty = t >> 4;
    int m0 = blockIdx.y * 64, n0 = blockIdx.x * 64;
    int ar = t >> 2, ac = (t & 3) * 4;
    int br = t >> 4, bc = (t & 15) * 4;
    float s[4][4] = {};
    for (int k0 = 0; k0 < K; k0 += 16) {
        float4 av = make_float4(0.f, 0.f, 0.f, 0.f);
        if (m0 + ar < M)
            av = *(const float4*)(A + (size_t)(m0 + ar) * lda + k0 + ac);
        float4 bv = *(const float4*)(B + (size_t)(k0 + br) * ldb + n0 + bc);
        __syncthreads();
        As[ac + 0][ar] = av.x; As[ac + 1][ar] = av.y;
        As[ac + 2][ar] = av.z; As[ac + 3][ar] = av.w;
        *(float4*)&Bs[br][bc] = bv;
        __syncthreads();
#pragma unroll
        for (int kk = 0; kk < 16; kk++) {
            float4 a = *(const float4*)&As[kk][ty * 4];
            float4 b = *(const float4*)&Bs[kk][tx * 4];
            s[0][0] += a.x * b.x; s[0][1] += a.x * b.y; s[0][2] += a.x * b.z; s[0][3] += a.x * b.w;
            s[1][0] += a.y * b.x; s[1][1] += a.y * b.y; s[1][2] += a.y * b.z; s[1][3] += a.y * b.w;
            s[2][0] += a.z * b.x; s[2][1] += a.z * b.y; s[2][2] += a.z * b.z; s[2][3] += a.z * b.w;
            s[3][0] += a.w * b.x; s[3][1] += a.w * b.y; s[3][2] += a.w * b.z; s[3][3] += a.w * b.w;
        }
    }
#pragma unroll
    for (int i = 0; i < 4; i++) {
        int m = m0 + ty * 4 + i;
        if (m < M) {
            float* cp = C + (size_t)m * ldc + n0 + tx * 4;
#pragma unroll
            for (int j = 0; j < 4; j++) cp[j] = s[i][j];
        }
    }
}

// ---------------- hi/lo split helpers (fp16) ----------------
__device__ __forceinline__ void split_h(float v, half* hi, half* lo, long o) {
    half h = __float2half_rn(v);
    hi[o] = h;
    lo[o] = __float2half_rn(v - __half2float(h));
}

// vectorized split: 4 floats per thread
__global__ void split_kernel(const float4* __restrict__ src, uint2* __restrict__ hi,
                             uint2* __restrict__ lo, int n4) {
    int i = blockIdx.x * 256 + threadIdx.x;
    if (i >= n4) return;
    float4 v = src[i];
    half h0 = __float2half_rn(v.x), h1 = __float2half_rn(v.y);
    half h2 = __float2half_rn(v.z), h3 = __float2half_rn(v.w);
    half2 hA = __halves2half2(h0, h1), hB = __halves2half2(h2, h3);
    half2 lA = __floats2half2_rn(v.x - __half2float(h0), v.y - __half2float(h1));
    half2 lB = __floats2half2_rn(v.z - __half2float(h2), v.w - __half2float(h3));
    uint2 ho, lw;
    ho.x = *(uint32_t*)&hA; ho.y = *(uint32_t*)&hB;
    lw.x = *(uint32_t*)&lA; lw.y = *(uint32_t*)&lB;
    hi[i] = ho;
    lo[i] = lw;
}

__global__ void tsplit_kernel(const float* __restrict__ src, int K, int N,
                              half* __restrict__ hi, half* __restrict__ lo) {
    __shared__ float tile[32][33];
    int n0 = blockIdx.x * 32, k0 = blockIdx.y * 32;
    int tx = threadIdx.x & 31, ty = threadIdx.x >> 5;
#pragma unroll
    for (int i = 0; i < 32; i += 8)
        tile[ty + i][tx] = src[(long)(k0 + ty + i) * N + n0 + tx];
    __syncthreads();
#pragma unroll
    for (int i = 0; i < 32; i += 8) {
        float v = tile[tx][ty + i];
        long o = (long)(n0 + ty + i) * K + k0 + tx;
        split_h(v, hi, lo, o);
    }
}

__global__ void rkt_kernel(const float* __restrict__ rK, half* rkth, half* rktl) {
    long i = (long)blockIdx.x * 256 + threadIdx.x;
    if (i >= (long)Hn * Lp * DKn) return;
    int d = (int)(i & 63);
    int l = (int)((i >> 6) % Lp);
    int h = (int)(i / ((long)Lp * DKn));
    float v = (l < Ln) ? rK[(long)l * HDK + h * DKn + d] : 0.f;
    split_h(v, rkth, rktl, i);
}

__global__ void vt_kernel(const float* __restrict__ Vf, half* vth, half* vtl) {
    __shared__ float tile[32][33];
    int z = blockIdx.z, h = z & 7, b = z >> 3;
    int t0 = blockIdx.x * 32, d0 = blockIdx.y * 32;
    int tx = threadIdx.x & 31, ty = threadIdx.x >> 5;
#pragma unroll
    for (int i = 0; i < 32; i += 8)
        tile[ty + i][tx] = Vf[((long)(b * Tn + t0 + ty + i)) * HDV + h * DVn + d0 + tx];
    __syncthreads();
#pragma unroll
    for (int i = 0; i < 32; i += 8) {
        float v = tile[tx][ty + i];
        long o = ((long)z * DVn + d0 + ty + i) * Tn + t0 + tx;
        split_h(v, vth, vtl, o);
    }
}

// ============================================================
// mma.sync fp16 GEMM (general):
//   NPASS 3: ah.bh+ah.bl+al.bh   NPASS 2: ah.bh+ah.bl (A hi only)
//   MODE 0: fp32 C = scale*acc + bias    MODE 2: banded shifted store (rel)
// ============================================================
template <int NPASS, int MODE>
__global__ void __launch_bounds__(256) gemm_mma(
    const half* __restrict__ Ah, const half* __restrict__ Al, int lda, long sA8, long sA1,
    const half* __restrict__ Bh, const half* __restrict__ Bl, int ldb, long sB8, long sB1,
    void* __restrict__ Cv, int ldc, long sC8, long sC1,
    int Kdim, int Ncols, float scale, const float* __restrict__ bias)
{
    constexpr int NA = (NPASS == 3) ? 2 : 1;
    constexpr int TILEA = 128 * 80;
    constexpr int TILEB = 128 * 80;
    constexpr int STAGE = NA * TILEA + 2 * TILEB;

    extern __shared__ char smem[];
    uint32_t sb = smem_u32(smem);
    int tid = threadIdx.x, lane = tid & 31, wid = tid >> 5;
    int wm = wid >> 2, wn = wid & 3;
    int z = blockIdx.z;
    int m0 = blockIdx.y * 128, n0 = blockIdx.x * 128;

    long zo_a = (long)(z >> 3) * sA8 + (long)(z & 7) * sA1;
    long zo_b = (long)(z >> 3) * sB8 + (long)(z & 7) * sB1;
    long zo_c = (long)(z >> 3) * sC8 + (long)(z & 7) * sC1;
    const half* pAh = Ah + zo_a + (long)m0 * lda;
    const half* pAl = Al + zo_a + (long)m0 * lda;
    long boff = (MODE == 2) ? (long)(Tn - 128 - m0 + n0) : (long)n0;
    const half* pBh = Bh + zo_b + boff * ldb;
    const half* pBl = Bl + zo_b + boff * ldb;

    float acc[4][4][4] = {};
    const int NC = Kdim >> 5;

    auto prefetch = [&](int kc) {
        int k0 = kc * 32;
        uint32_t s0 = sb + (kc & 1) * STAGE;
        for (int i = tid; i < 512; i += 256) {
            int r = i >> 2, c = i & 3;
            uint32_t so = (uint32_t)(r * 80 + c * 16);
            long go = (long)r * lda + k0 + c * 8;
            cp16(s0 + so, pAh + go);
            if (NPASS == 3) cp16(s0 + TILEA + so, pAl + go);
            long gb = (long)r * ldb + k0 + c * 8;
            cp16(s0 + NA * TILEA + so,         pBh + gb);
            cp16(s0 + NA * TILEA + TILEB + so, pBl + gb);
        }
        CP_COMMIT();
    };

    prefetch(0);
    for (int kc = 0; kc < NC; kc++) {
        CP_WAIT(0);
        __syncthreads();
        if (kc + 1 < NC) prefetch(kc + 1);
        uint32_t s0 = sb + (kc & 1) * STAGE;

#pragma unroll
        for (int kk = 0; kk < 2; kk++) {
            int k16 = kk * 16;
            uint32_t ah[4][4], al4[4][4], bh[4][2], bl4[4][2];
            uint32_t arow = (uint32_t)(wm * 64 + (lane & 15));
            uint32_t acol = (uint32_t)(k16 + (lane >> 4) * 8);
#pragma unroll
            for (int mi = 0; mi < 4; mi++) {
                uint32_t ao = s0 + (arow + mi * 16) * 80 + acol * 2;
                LDSM4(ah[mi], ao);
                if (NPASS == 3) LDSM4(al4[mi], ao + TILEA);
            }
            uint32_t brow = (uint32_t)(wn * 32 + (lane & 7) + ((lane >> 4) & 1) * 8);
            uint32_t bcol = (uint32_t)(k16 + ((lane >> 3) & 1) * 8);
#pragma unroll
            for (int g = 0; g < 2; g++) {
                uint32_t t4[4];
                uint32_t bo = s0 + NA * TILEA + (brow + g * 16) * 80 + bcol * 2;
                LDSM4(t4, bo);
                bh[g * 2][0] = t4[0]; bh[g * 2][1] = t4[1];
                bh[g * 2 + 1][0] = t4[2]; bh[g * 2 + 1][1] = t4[3];
                LDSM4(t4, bo + TILEB);
                bl4[g * 2][0] = t4[0]; bl4[g * 2][1] = t4[1];
                bl4[g * 2 + 1][0] = t4[2]; bl4[g * 2 + 1][1] = t4[3];
            }
#pragma unroll
            for (int mi = 0; mi < 4; mi++)
#pragma unroll
                for (int ni = 0; ni < 4; ni++) {
                    MMA(acc[mi][ni], ah[mi], bh[ni]);
                    MMA(acc[mi][ni], ah[mi], bl4[ni]);
                    if (NPASS == 3) MMA(acc[mi][ni], al4[mi], bh[ni]);
                }
        }
        __syncthreads();
    }

    int gID = lane >> 2, tig = lane & 3;
#pragma unroll
    for (int mi = 0; mi < 4; mi++) {
#pragma unroll
        for (int ni = 0; ni < 4; ni++) {
            int rloc = wm * 64 + mi * 16 + gID;
            int coll = wn * 32 + ni * 8 + tig * 2;
            int row0 = m0 + rloc;
            int col  = n0 + coll;
            if (MODE == 0) {
                float* Cf = (float*)Cv;
                if (col < Ncols) {
                    float b0 = bias ? bias[col] : 0.f;
                    float b1 = bias ? bias[col + 1] : 0.f;
                    float* p0 = Cf + zo_c + (long)row0 * ldc + col;
                    float* p1 = Cf + zo_c + (long)(row0 + 8) * ldc + col;
                    *(float2*)p0 = make_float2(acc[mi][ni][0] * scale + b0, acc[mi][ni][1] * scale + b1);
                    *(float2*)p1 = make_float2(acc[mi][ni][2] * scale + b0, acc[mi][ni][3] * scale + b1);
                }
            } else {
                float* Cf = (float*)Cv;
                int k0a = n0 + coll + rloc - 127;
                int k0b = k0a + 8;
                float* r0p = Cf + zo_c + (long)row0 * ldc;
                float* r1p = r0p + 8L * ldc;
                if (k0a >= 0     && k0a < Tn)     r0p[k0a]     = acc[mi][ni][0];
                if (k0a + 1 >= 0 && k0a + 1 < Tn) r0p[k0a + 1] = acc[mi][ni][1];
                if (k0b >= 0     && k0b < Tn)     r1p[k0b]     = acc[mi][ni][2];
                if (k0b + 1 >= 0 && k0b + 1 < Tn) r1p[k0b + 1] = acc[mi][ni][3];
            }
        }
    }
}

// ============================================================
// fused Q+K projection (R7 winner, unchanged)
// ============================================================
__global__ void __launch_bounds__(256) qkproj_kernel(
    const half* __restrict__ Ah, const half* __restrict__ Al,
    const half* __restrict__ Bh, const half* __restrict__ Bl,
    const float* __restrict__ rwb, const float* __restrict__ rrb,
    half* __restrict__ qwh, half* __restrict__ qwl,
    half* __restrict__ qrh, half* __restrict__ qrl,
    half* __restrict__ kh,  half* __restrict__ kl)
{
    constexpr int TILEA = 128 * 80;
    constexpr int TILEB = 128 * 80;
    constexpr int STAGE = 2 * TILEA + 2 * TILEB;

    extern __shared__ char smem[];
    uint32_t sb = smem_u32(smem);
    int tid = threadIdx.x, lane = tid & 31, wid = tid >> 5;
    int wm = wid >> 2, wn = wid & 3;
    int m0 = blockIdx.y * 128, n0 = blockIdx.x * 128;
    int bIdx = m0 / Tn, t0 = m0 % Tn;

    const half* pAh = Ah + (long)m0 * Cin;
    const half* pAl = Al + (long)m0 * Cin;
    const half* pBh = Bh + (long)n0 * Cin;
    const half* pBl = Bl + (long)n0 * Cin;

    float acc[4][4][4] = {};
    const int NC = Cin >> 5;

    auto prefetch = [&](int kc) {
        int k0 = kc * 32;
        uint32_t s0 = sb + (kc & 1) * STAGE;
        for (int i = tid; i < 512; i += 256) {
            int r = i >> 2, c = i & 3;
            uint32_t so = (uint32_t)(r * 80 + c * 16);
            long go = (long)r * Cin + k0 + c * 8;
            cp16(s0 + so,         pAh + go);
            cp16(s0 + TILEA + so, pAl + go);
            cp16(s0 + 2 * TILEA + so,         pBh + go);
            cp16(s0 + 2 * TILEA + TILEB + so, pBl + go);
        }
        CP_COMMIT();
    };

    prefetch(0);
    for (int kc = 0; kc < NC; kc++) {
        CP_WAIT(0);
        __syncthreads();
        if (kc + 1 < NC) prefetch(kc + 1);
        uint32_t s0 = sb + (kc & 1) * STAGE;

#pragma unroll
        for (int kk = 0; kk < 2; kk++) {
            int k16 = kk * 16;
            uint32_t ah[4][4], al4[4][4], bh[4][2], bl4[4][2];
            uint32_t arow = (uint32_t)(wm * 64 + (lane & 15));
            uint32_t acol = (uint32_t)(k16 + (lane >> 4) * 8);
#pragma unroll
            for (int mi = 0; mi < 4; mi++) {
                uint32_t ao = s0 + (arow + mi * 16) * 80 + acol * 2;
                LDSM4(ah[mi], ao);
                LDSM4(al4[mi], ao + TILEA);
            }
            uint32_t brow = (uint32_t)(wn * 32 + (lane & 7) + ((lane >> 4) & 1) * 8);
            uint32_t bcol = (uint32_t)(k16 + ((lane >> 3) & 1) * 8);
#pragma unroll
            for (int g = 0; g < 2; g++) {
                uint32_t t4[4];
                uint32_t bo = s0 + 2 * TILEA + (brow + g * 16) * 80 + bcol * 2;
                LDSM4(t4, bo);
                bh[g * 2][0] = t4[0]; bh[g * 2][1] = t4[1];
                bh[g * 2 + 1][0] = t4[2]; bh[g * 2 + 1][1] = t4[3];
                LDSM4(t4, bo + TILEB);
                bl4[g * 2][0] = t4[0]; bl4[g * 2][1] = t4[1];
                bl4[g * 2 + 1][0] = t4[2]; bl4[g * 2 + 1][1] = t4[3];
            }
#pragma unroll
            for (int mi = 0; mi < 4; mi++)
#pragma unroll
                for (int ni = 0; ni < 4; ni++) {
                    MMA(acc[mi][ni], ah[mi], bh[ni]);
                    MMA(acc[mi][ni], ah[mi], bl4[ni]);
                    MMA(acc[mi][ni], al4[mi], bh[ni]);
                }
        }
        __syncthreads();
    }

    int gID = lane >> 2, tig = lane & 3;
#pragma unroll
    for (int mi = 0; mi < 4; mi++) {
#pragma unroll
        for (int ni = 0; ni < 4; ni++) {
            int rloc = wm * 64 + mi * 16 + gID;
            int coll = wn * 32 + ni * 8 + tig * 2;
            int col  = n0 + coll;
#pragma unroll
            for (int half_i = 0; half_i < 2; half_i++) {
                int t = t0 + rloc + half_i * 8;
                float v0 = acc[mi][ni][half_i * 2 + 0];
                float v1 = acc[mi][ni][half_i * 2 + 1];
                if (col < 512) {
                    int h = col >> 6, d = col & 63;
                    long o = ((long)(bIdx * 8 + h) * Tn + t) * 64 + d;
                    float q0 = v0 * 0.125f, q1 = v1 * 0.125f;
                    float w0 = q0 + rwb[col], w1 = q1 + rwb[col + 1];
                    float r0 = q0 + rrb[col], r1 = q1 + rrb[col + 1];
                    half wh0 = __float2half_rn(w0), wh1 = __float2half_rn(w1);
                    half rh0 = __float2half_rn(r0), rh1 = __float2half_rn(r1);
                    *(half2*)(qwh + o) = __halves2half2(wh0, wh1);
                    *(half2*)(qwl + o) = __floats2half2_rn(w0 - __half2float(wh0), w1 - __half2float(wh1));
                    *(half2*)(qrh + o) = __halves2half2(rh0, rh1);
                    *(half2*)(qrl + o) = __floats2half2_rn(r0 - __half2float(rh0), r1 - __half2float(rh1));
                } else {
                    int ck = col - 512;
                    int h = ck >> 6, d = ck & 63;
                    long o = ((long)(bIdx * 8 + h) * Tn + t) * 64 + d;
                    half kh0 = __float2half_rn(v0), kh1 = __float2half_rn(v1);
                    *(half2*)(kh + o) = __halves2half2(kh0, kh1);
                    *(half2*)(kl + o) = __floats2half2_rn(v0 - __half2float(kh0), v1 - __half2float(kh1));
                }
            }
        }
    }
}

// ============================================================
// flash kernel (R6/R7 winner; z0 offset added for split launch)
// ============================================================
__global__ void __launch_bounds__(256) flash_kernel(
    const half* __restrict__ qwh_, const half* __restrict__ qwl_,
    const half* __restrict__ kh_,  const half* __restrict__ kl_,
    const half* __restrict__ vth_, const half* __restrict__ vtl_,
    const float* __restrict__ logits, half* __restrict__ aoh, int z0)
{
    extern __shared__ char smem[];
    uint32_t sb = smem_u32(smem);
    const uint32_t QB = sb, KB = sb + 40960, PB = sb + 81920, VB = sb + 122880;
    float* mArr = (float*)(smem + 184320);
    float* lArr = mArr + 128;
    float* aArr = lArr + 128;
    float* red  = aArr + 128;   // [128][4]

    int tid = threadIdx.x, lane = tid & 31, wid = tid >> 5;
    int wm = wid >> 2, wn = wid & 3;
    int wm2 = wid >> 1, wn2 = wid & 1;
    int gID = lane >> 2, tig = lane & 3;
    int z = blockIdx.z + z0;
    int q0 = blockIdx.y * 128;
    int h = z & 7, b = z >> 3;

    long zq = (long)z * Tn * DKn;
    const half* pQh = qwh_ + zq + (long)q0 * DKn;
    const half* pQl = qwl_ + zq + (long)q0 * DKn;
    const half* pKh = kh_ + zq;
    const half* pKl = kl_ + zq;
    long zv = (long)z * DVn * Tn;
    const float* pL = logits + (long)z * Tn * Tn + (long)q0 * Tn;

    for (int r = tid; r < 128; r += 256) { mArr[r] = -1e30f; lArr[r] = 0.f; }

    for (int i = tid; i < 1024; i += 256) {
        int r = i >> 3, c = i & 7;
        uint32_t off = (uint32_t)((c >> 2) * 10240 + r * 80 + (c & 3) * 16);
        cp16(QB + off,         pQh + (long)r * DKn + c * 8);
        cp16(QB + 20480 + off, pQl + (long)r * DKn + c * 8);
        cp16(KB + off,         pKh + (long)r * DKn + c * 8);
        cp16(KB + 20480 + off, pKl + (long)r * DKn + c * 8);
    }
    CP_COMMIT();

    float O[2][12][4] = {};

    auto loadK = [&](int kn) {
        const half* gh = pKh + (long)kn * 128 * DKn;
        const half* gl = pKl + (long)kn * 128 * DKn;
        for (int i = tid; i < 1024; i += 256) {
            int r = i >> 3, c = i & 7;
            uint32_t off = (uint32_t)((c >> 2) * 10240 + r * 80 + (c & 3) * 16);
            cp16(KB + off,         gh + (long)r * DKn + c * 8);
            cp16(KB + 20480 + off, gl + (long)r * DKn + c * 8);
        }
        CP_COMMIT();
    };

    for (int kt = 0; kt < 12; kt++) {
        CP_WAIT(0);
        __syncthreads();

        float S[4][4][4] = {};
#pragma unroll
        for (int chunk = 0; chunk < 2; chunk++) {
            uint32_t qbase = QB + chunk * 10240;
            uint32_t kbase = KB + chunk * 10240;
#pragma unroll
            for (int kk = 0; kk < 2; kk++) {
                int k16 = kk * 16;
                uint32_t ah[4][4], al4[4][4], bh[4][2], bl4[4][2];
                uint32_t arow = (uint32_t)(wm * 64 + (lane & 15));
                uint32_t acol = (uint32_t)(k16 + (lane >> 4) * 8);
#pragma unroll
                for (int mi = 0; mi < 4; mi++) {
                    uint32_t ao = qbase + (arow + mi * 16) * 80 + acol * 2;
                    LDSM4(ah[mi], ao);
                    LDSM4(al4[mi], ao + 20480);
                }
                uint32_t brow = (uint32_t)(wn * 32 + (lane & 7) + ((lane >> 4) & 1) * 8);
                uint32_t bcol = (uint32_t)(k16 + ((lane >> 3) & 1) * 8);
#pragma unroll
                for (int g = 0; g < 2; g++) {
                    uint32_t t4[4];
                    uint32_t bo = kbase + (brow + g * 16) * 80 + bcol * 2;
                    LDSM4(t4, bo);
                    bh[g * 2][0] = t4[0]; bh[g * 2][1] = t4[1];
                    bh[g * 2 + 1][0] = t4[2]; bh[g * 2 + 1][1] = t4[3];
                    LDSM4(t4, bo + 20480);
                    bl4[g * 2][0] = t4[0]; bl4[g * 2][1] = t4[1];
                    bl4[g * 2 + 1][0] = t4[2]; bl4[g * 2 + 1][1] = t4[3];
                }
#pragma unroll
                for (int mi = 0; mi < 4; mi++)
#pragma unroll
                    for (int ni = 0; ni < 4; ni++) {
                        MMA(S[mi][ni], ah[mi], bh[ni]);
                        MMA(S[mi][ni], ah[mi], bl4[ni]);
                        MMA(S[mi][ni], al4[mi], bh[ni]);
                    }
            }
        }

#pragma unroll
        for (int mi = 0; mi < 4; mi++) {
            int r0 = wm * 64 + mi * 16 + gID;
#pragma unroll
            for (int ni = 0; ni < 4; ni++) {
                long coff = (long)kt * 128 + wn * 32 + ni * 8 + tig * 2;
                float2 v0 = *(const float2*)(pL + (long)r0 * Tn + coff);
                float2 v1 = *(const float2*)(pL + (long)(r0 + 8) * Tn + coff);
                S[mi][ni][0] += v0.x; S[mi][ni][1] += v0.y;
                S[mi][ni][2] += v1.x; S[mi][ni][3] += v1.y;
            }
        }

#pragma unroll
        for (int mi = 0; mi < 4; mi++) {
            float m0v = -1e30f, m1v = -1e30f;
#pragma unroll
            for (int ni = 0; ni < 4; ni++) {
                m0v = fmaxf(m0v, fmaxf(S[mi][ni][0], S[mi][ni][1]));
                m1v = fmaxf(m1v, fmaxf(S[mi][ni][2], S[mi][ni][3]));
            }
            m0v = fmaxf(m0v, __shfl_xor_sync(0xffffffffu, m0v, 1));
            m0v = fmaxf(m0v, __shfl_xor_sync(0xffffffffu, m0v, 2));
            m1v = fmaxf(m1v, __shfl_xor_sync(0xffffffffu, m1v, 1));
            m1v = fmaxf(m1v, __shfl_xor_sync(0xffffffffu, m1v, 2));
            if (tig == 0) {
                int r0 = wm * 64 + mi * 16 + gID;
                red[r0 * 4 + wn] = m0v;
                red[(r0 + 8) * 4 + wn] = m1v;
            }
        }
        __syncthreads();

        float mns0[4], mns1[4], alp0[4], alp1[4], sum0[4], sum1[4];
#pragma unroll
        for (int mi = 0; mi < 4; mi++) {
            int r0 = wm * 64 + mi * 16 + gID, r1 = r0 + 8;
            float mo0 = mArr[r0], mo1 = mArr[r1];
            float mn0 = mo0, mn1 = mo1;
#pragma unroll
            for (int w = 0; w < 4; w++) {
                mn0 = fmaxf(mn0, red[r0 * 4 + w]);
                mn1 = fmaxf(mn1, red[r1 * 4 + w]);
            }
            float s0 = 0.f, s1 = 0.f;
#pragma unroll
            for (int ni = 0; ni < 4; ni++) {
                S[mi][ni][0] = __expf(S[mi][ni][0] - mn0);
                S[mi][ni][1] = __expf(S[mi][ni][1] - mn0);
                S[mi][ni][2] = __expf(S[mi][ni][2] - mn1);
                S[mi][ni][3] = __expf(S[mi][ni][3] - mn1);
                s0 += S[mi][ni][0] + S[mi][ni][1];
                s1 += S[mi][ni][2] + S[mi][ni][3];
            }
            s0 += __shfl_xor_sync(0xffffffffu, s0, 1);
            s0 += __shfl_xor_sync(0xffffffffu, s0, 2);
            s1 += __shfl_xor_sync(0xffffffffu, s1, 1);
            s1 += __shfl_xor_sync(0xffffffffu, s1, 2);
            mns0[mi] = mn0; mns1[mi] = mn1;
            alp0[mi] = __expf(mo0 - mn0); alp1[mi] = __expf(mo1 - mn1);
            sum0[mi] = s0; sum1[mi] = s1;
        }
        __syncthreads();

#pragma unroll
        for (int mi = 0; mi < 4; mi++) {
            int r0 = wm * 64 + mi * 16 + gID, r1 = r0 + 8;
            if (tig == 0) {
                red[r0 * 4 + wn] = sum0[mi];
                red[r1 * 4 + wn] = sum1[mi];
                if (wn == 0) { aArr[r0] = alp0[mi]; aArr[r1] = alp1[mi]; }
            }
#pragma unroll
            for (int ni = 0; ni < 4; ni++) {
                int colin = ni * 8 + tig * 2;
                half2 h0 = __floats2half2_rn(S[mi][ni][0], S[mi][ni][1]);
                half2 h1 = __floats2half2_rn(S[mi][ni][2], S[mi][ni][3]);
                uint32_t p0 = PB + wn * 10240 + r0 * 80 + colin * 2;
                uint32_t p1 = PB + wn * 10240 + r1 * 80 + colin * 2;
                STS32(p0, *(uint32_t*)&h0);
                STS32(p1, *(uint32_t*)&h1);
            }
        }
        __syncthreads();

        if (wn == 0 && tig == 0) {
#pragma unroll
            for (int mi = 0; mi < 4; mi++) {
                int r0 = wm * 64 + mi * 16 + gID, r1 = r0 + 8;
                lArr[r0] = lArr[r0] * alp0[mi] + red[r0 * 4 + 0] + red[r0 * 4 + 1] + red[r0 * 4 + 2] + red[r0 * 4 + 3];
                lArr[r1] = lArr[r1] * alp1[mi] + red[r1 * 4 + 0] + red[r1 * 4 + 1] + red[r1 * 4 + 2] + red[r1 * 4 + 3];
                mArr[r0] = mns0[mi];
                mArr[r1] = mns1[mi];
            }
        }

        {
            const half* gh = vth_ + zv + (long)kt * 128;
            const half* gl = vtl_ + zv + (long)kt * 128;
            for (int cc2 = 0; cc2 < 2; cc2++) {
                uint32_t vb = VB + cc2 * 30720;
                for (int i = tid; i < 768; i += 256) {
                    int r = i >> 2, c4 = i & 3;
                    uint32_t off = (uint32_t)(r * 80 + c4 * 16);
                    cp16(vb + off,         gh + (long)r * Tn + cc2 * 32 + c4 * 8);
                    cp16(vb + 15360 + off, gl + (long)r * Tn + cc2 * 32 + c4 * 8);
                }
                CP_COMMIT();
            }
            loadK((kt + 1 < 12) ? kt + 1 : 11);
        }

#pragma unroll
        for (int mi = 0; mi < 2; mi++) {
            float a0 = aArr[wm2 * 32 + mi * 16 + gID];
            float a1 = aArr[wm2 * 32 + mi * 16 + gID + 8];
#pragma unroll
            for (int ni = 0; ni < 12; ni++) {
                O[mi][ni][0] *= a0; O[mi][ni][1] *= a0;
                O[mi][ni][2] *= a1; O[mi][ni][3] *= a1;
            }
        }

        auto pvChunk = [&](int c) {
            uint32_t pb = PB + c * 10240;
            uint32_t vb = VB + (c & 1) * 30720;
#pragma unroll
            for (int kk = 0; kk < 2; kk++) {
                int k16 = kk * 16;
                uint32_t pa[2][4], vh[12][2], vl[12][2];
                uint32_t arow = (uint32_t)(wm2 * 32 + (lane & 15));
                uint32_t acol = (uint32_t)(k16 + (lane >> 4) * 8);
#pragma unroll
                for (int mi = 0; mi < 2; mi++)
                    LDSM4(pa[mi], pb + (arow + mi * 16) * 80 + acol * 2);
                uint32_t brow = (uint32_t)(wn2 * 96 + (lane & 7) + ((lane >> 4) & 1) * 8);
                uint32_t bcol = (uint32_t)(k16 + ((lane >> 3) & 1) * 8);
#pragma unroll
                for (int g = 0; g < 6; g++) {
                    uint32_t t4[4];
                    uint32_t bo = vb + (brow + g * 16) * 80 + bcol * 2;
                    LDSM4(t4, bo);
                    vh[g * 2][0] = t4[0]; vh[g * 2][1] = t4[1];
                    vh[g * 2 + 1][0] = t4[2]; vh[g * 2 + 1][1] = t4[3];
                    LDSM4(t4, bo + 15360);
                    vl[g * 2][0] = t4[0]; vl[g * 2][1] = t4[1];
                    vl[g * 2 + 1][0] = t4[2]; vl[g * 2 + 1][1] = t4[3];
                }
#pragma unroll
                for (int mi = 0; mi < 2; mi++)
#pragma unroll
                    for (int ni = 0; ni < 12; ni++) {
                        MMA(O[mi][ni], pa[mi], vh[ni]);
                        MMA(O[mi][ni], pa[mi], vl[ni]);
                    }
            }
        };
        auto loadV = [&](int c) {
            uint32_t vb = VB + (c & 1) * 30720;
            const half* gh = vth_ + zv + (long)kt * 128 + c * 32;
            const half* gl = vtl_ + zv + (long)kt * 128 + c * 32;
            for (int i = tid; i < 768; i += 256) {
                int r = i >> 2, c4 = i & 3;
                uint32_t off = (uint32_t)(r * 80 + c4 * 16);
                cp16(vb + off,         gh + (long)r * Tn + c4 * 8);
                cp16(vb + 15360 + off, gl + (long)r * Tn + c4 * 8);
            }
            CP_COMMIT();
        };

        CP_WAIT(2); __syncthreads();
        pvChunk(0);
        __syncthreads(); loadV(2);
        CP_WAIT(2); __syncthreads();
        pvChunk(1);
        __syncthreads(); loadV(3);
        CP_WAIT(1); __syncthreads();
        pvChunk(2);
        CP_WAIT(0); __syncthreads();
        pvChunk(3);
    }

    __syncthreads();
#pragma unroll
    for (int mi = 0; mi < 2; mi++) {
        int rl0 = wm2 * 32 + mi * 16 + gID, rl1 = rl0 + 8;
        float i0 = 1.f / lArr[rl0], i1 = 1.f / lArr[rl1];
        long base0 = ((long)(b * Tn + q0 + rl0)) * HDV + h * 192;
        long base1 = ((long)(b * Tn + q0 + rl1)) * HDV + h * 192;
#pragma unroll
        for (int ni = 0; ni < 12; ni++) {
            int col = wn2 * 96 + ni * 8 + tig * 2;
            *(half2*)(aoh + base0 + col) = __floats2half2_rn(O[mi][ni][0] * i0, O[mi][ni][1] * i0);
            *(half2*)(aoh + base1 + col) = __floats2half2_rn(O[mi][ni][2] * i1, O[mi][ni][3] * i1);
        }
    }
}

// ---------------- launch: forked-stream DAG ----------------
extern "C" void kernel_launch(void* const* d_in, const int* in_sizes, int n_in,
                              void* d_out, int out_size) {
    const float* x       = (const float*)d_in[0];
    const float* W_q     = (const float*)d_in[1];
    const float* W_k     = (const float*)d_in[2];
    const float* W_v     = (const float*)d_in[3];
    const float* W_rel_k = (const float*)d_in[4];
    const float* W_out   = (const float*)d_in[5];
    const float* b_out   = (const float*)d_in[6];
    const float* rwb     = (const float*)d_in[7];
    const float* rrb     = (const float*)d_in[8];
    float* out = (float*)d_out;

    float *pe, *rK, *Vf, *logits;
    double* gmax;
    half *xh, *xl, *wqkh, *wqkl, *wvth, *wvtl, *woth, *wotl;
    half *qwh, *qwl, *qrh, *qrl, *kh, *kl, *rkth, *rktl, *vth, *vtl, *aoh;
    cudaGetSymbolAddress((void**)&pe, g_pe);
    cudaGetSymbolAddress((void**)&rK, g_rK);
    cudaGetSymbolAddress((void**)&gmax, g_gmax);
    cudaGetSymbolAddress((void**)&Vf, g_Vf);
    cudaGetSymbolAddress((void**)&xh, g_xh);   cudaGetSymbolAddress((void**)&xl, g_xl);
    cudaGetSymbolAddress((void**)&wqkh, g_wqkh); cudaGetSymbolAddress((void**)&wqkl, g_wqkl);
    cudaGetSymbolAddress((void**)&wvth, g_wvth); cudaGetSymbolAddress((void**)&wvtl, g_wvtl);
    cudaGetSymbolAddress((void**)&woth, g_woth); cudaGetSymbolAddress((void**)&wotl, g_wotl);
    cudaGetSymbolAddress((void**)&qwh, g_qwh); cudaGetSymbolAddress((void**)&qwl, g_qwl);
    cudaGetSymbolAddress((void**)&qrh, g_qrh); cudaGetSymbolAddress((void**)&qrl, g_qrl);
    cudaGetSymbolAddress((void**)&kh, g_kh);   cudaGetSymbolAddress((void**)&kl, g_kl);
    cudaGetSymbolAddress((void**)&rkth, g_rkth); cudaGetSymbolAddress((void**)&rktl, g_rktl);
    cudaGetSymbolAddress((void**)&vth, g_vth); cudaGetSymbolAddress((void**)&vtl, g_vtl);
    cudaGetSymbolAddress((void**)&logits, g_logits);
    cudaGetSymbolAddress((void**)&aoh, g_aoh);

    const int SM_3 = 2 * (2 * 128 * 80 + 2 * 128 * 80);  // 81920
    const int SM_2 = 2 * (1 * 128 * 80 + 2 * 128 * 80);  // 61440
    const int SM_F = 187904;

    static bool inited = false;
    static cudaStream_t s1, s2;
    static cudaEvent_t evStart, evX, evRK, evVT, evRel, evD2;
    if (!inited) {
        cudaStreamCreateWithFlags(&s1, cudaStreamNonBlocking);
        cudaStreamCreateWithFlags(&s2, cudaStreamNonBlocking);
        cudaEventCreateWithFlags(&evStart, cudaEventDisableTiming);
        cudaEventCreateWithFlags(&evX, cudaEventDisableTiming);
        cudaEventCreateWithFlags(&evRK, cudaEventDisableTiming);
        cudaEventCreateWithFlags(&evVT, cudaEventDisableTiming);
        cudaEventCreateWithFlags(&evRel, cudaEventDisableTiming);
        cudaEventCreateWithFlags(&evD2, cudaEventDisableTiming);
        cudaFuncSetAttribute(gemm_mma<3, 2>, cudaFuncAttributeMaxDynamicSharedMemorySize, SM_3);
        cudaFuncSetAttribute(gemm_mma<2, 0>, cudaFuncAttributeMaxDynamicSharedMemorySize, SM_2);
        cudaFuncSetAttribute(qkproj_kernel, cudaFuncAttributeMaxDynamicSharedMemorySize, SM_3);
        cudaFuncSetAttribute(flash_kernel, cudaFuncAttributeMaxDynamicSharedMemorySize, SM_F);
        inited = true;
    }

    long sQ = (long)Tn * DKn;
    long sR = (long)Lp * DKn;

    // ---- fork ----
    cudaEventRecord(evStart, 0);
    cudaStreamWaitEvent(s1, evStart, 0);
    cudaStreamWaitEvent(s2, evStart, 0);

    // s1: positional basis chain -> rkt  (independent until rel)
    gamma_max_kernel<<<32, 256, 0, s1>>>(gmax);
    pe_kernel<<<(Ln * 32 + 255) / 256, 256, 0, s1>>>(gmax, pe);
    sgemm_kernel<<<dim3(HDK / 64, (Ln + 63) / 64), 256, 0, s1>>>(
        pe, 192, W_rel_k, HDK, rK, HDK, Ln, HDK, 192);
    rkt_kernel<<<(int)(((long)Hn * Lp * DKn + 255) / 256), 256, 0, s1>>>(rK, rkth, rktl);
    cudaEventRecord(evRK, s1);

    // s2: W_v tsplit (no deps)
    tsplit_kernel<<<dim3(HDV / 32, Cin / 32), 256, 0, s2>>>(W_v, Cin, HDV, wvth, wvtl);

    // s0: x split
    split_kernel<<<(BT * Cin / 4 + 255) / 256, 256>>>(
        (const float4*)x, (uint2*)xh, (uint2*)xl, BT * Cin / 4);
    cudaEventRecord(evX, 0);
    cudaStreamWaitEvent(s2, evX, 0);

    // s2: V projection (2-pass) + head transpose
    gemm_mma<2, 0><<<dim3(HDV / 128, BT / 128, 1), 256, SM_2, s2>>>(
        xh, xh, Cin, 0, 0, wvth, wvtl, Cin, 0, 0, Vf, HDV, 0, 0, Cin, HDV, 1.0f, nullptr);
    vt_kernel<<<dim3(Tn / 32, DVn / 32, NBH), 256, 0, s2>>>(Vf, vth, vtl);
    cudaEventRecord(evVT, s2);

    // s0: weight tsplits + fused QK projection
    tsplit_kernel<<<dim3(HDK / 32, Cin / 32), 256>>>(W_q, Cin, HDK, wqkh, wqkl);
    tsplit_kernel<<<dim3(HDK / 32, Cin / 32), 256>>>(W_k, Cin, HDK,
                                                     wqkh + (long)512 * Cin, wqkl + (long)512 * Cin);
    tsplit_kernel<<<dim3(HDV / 32, HDV / 32), 256>>>(W_out, HDV, HDV, woth, wotl);
    qkproj_kernel<<<dim3(1024 / 128, BT / 128, 1), 256, SM_3>>>(
        xh, xl, wqkh, wqkl, rwb, rrb, qwh, qwl, qrh, qrl, kh, kl);

    // s0: rel (needs rkt from s1)
    cudaStreamWaitEvent(0, evRK, 0);
    gemm_mma<3, 2><<<dim3(13, Tn / 128, NBH), 256, SM_3>>>(
        qrh, qrl, DKn, 8 * sQ, sQ, rkth, rktl, DKn, 0, sR,
        logits, Tn, 8L * Tn * Tn, (long)Tn * Tn, DKn, Tn, 1.0f, nullptr);
    cudaEventRecord(evRel, 0);

    // s0: flash for b=0,1 (z 0..15), then its out-proj half
    cudaStreamWaitEvent(0, evVT, 0);
    flash_kernel<<<dim3(1, Tn / 128, 16), 256, SM_F>>>(
        qwh, qwl, kh, kl, vth, vtl, logits, aoh, 0);
    gemm_mma<2, 0><<<dim3(HDV / 128, 2 * Tn / 128, 1), 256, SM_2>>>(
        aoh, aoh, HDV, 0, 0, woth, wotl, HDV, 0, 0, out, HDV, 0, 0, HDV, HDV, 1.0f, b_out);

    // s2: flash for b=2,3 (z 16..31), then its out-proj half
    cudaStreamWaitEvent(s2, evRel, 0);
    flash_kernel<<<dim3(1, Tn / 128, 16), 256, SM_F, s2>>>(
        qwh, qwl, kh, kl, vth, vtl, logits, aoh, 16);
    gemm_mma<2, 0><<<dim3(HDV / 128, 2 * Tn / 128, 1), 256, SM_2, s2>>>(
        aoh + (long)2 * Tn * HDV, aoh + (long)2 * Tn * HDV, HDV, 0, 0,
        woth, wotl, HDV, 0, 0,
        out + (long)2 * Tn * HDV, HDV, 0, 0, HDV, HDV, 1.0f, b_out);
    cudaEventRecord(evD2, s2);

    // ---- join ----
    cudaStreamWaitEvent(0, evD2, 0);
}